// round 1
// baseline (speedup 1.0000x reference)
#include <cuda_runtime.h>
#include <cuda_bf16.h>
#include <math.h>

// ---------------- problem constants ----------------
#define Bq   2
#define Cc   128
#define Hf   256
#define Wf   256
#define Nf   (Hf*Wf)      // 65536
#define Hh   128
#define Wh   128
#define Nh2  (Hh*Wh)      // 16384
#define NHh  8
#define HD   16           // channels per head

#define HB   ((size_t)Bq*Cc*Nh2)   // one half-res (B,C,Hh,Wh) buffer: 4,194,304 floats

// ---------------- device scratch (no runtime alloc allowed) ----------------
__device__ float g_qkv [(size_t)Bq*3*Cc*Nf];   // conv1x1 qkv output
__device__ float g_qkvd[(size_t)Bq*3*Cc*Nf];   // depthwise conv output (q,k,v)
__device__ float g_hbuf[10*((size_t)Bq*Cc*Nh2)]; // half-res buffers
__device__ float g_masks[(size_t)Bq*5*Cc*Nh2];
__device__ float g_qcat [(size_t)Bq*2*Cc*Nh2];
__device__ float g_qfull[(size_t)Bq*Cc*Nf];
__device__ float g_gram [Bq*NHh*288];          // per (b,h): S[256], |q|^2[16], |k|^2[16]
__device__ float g_weff [Bq*Cc*Cc];

// =====================================================================
// conv1x1 as GEMM: out[o,p] = act( sum_c W[o,c]*in[c,p] + bias[o] )
// BM=BN=128, BK=8, 256 threads, 8x8 per thread.
// EPI: 0=bias, 1=sigmoid(bias+acc), 2=residual + (acc+bias)*mask
// =====================================================================
template<int EPI>
__global__ void __launch_bounds__(256) conv1x1_k(
    const float* __restrict__ in, const float* __restrict__ w,
    const float* __restrict__ bias, float* __restrict__ out,
    const float* __restrict__ mask,
    int Cin, int P,
    size_t inBS, size_t outBS, size_t wBS, size_t maskBS)
{
    const int b = blockIdx.z;
    in  += (size_t)b*inBS;
    out += (size_t)b*outBS;
    w   += (size_t)b*wBS;
    if (EPI == 2) mask += (size_t)b*maskBS;

    const int o0 = blockIdx.y*128;
    const int p0 = blockIdx.x*128;

    __shared__ float As[8][132];   // [k][o]
    __shared__ float Bs[8][132];   // [k][p]

    const int t  = threadIdx.x;
    const int ty = t >> 4;         // 0..15
    const int tx = t & 15;         // 0..15

    float acc[8][8];
#pragma unroll
    for (int i=0;i<8;i++)
#pragma unroll
        for (int j=0;j<8;j++) acc[i][j]=0.f;

    for (int k0=0; k0<Cin; k0+=8) {
#pragma unroll
        for (int i=0;i<4;i++) {
            int e = t + i*256;
            int c = e & 7, o = e >> 3;
            As[c][o] = w[(size_t)(o0+o)*Cin + k0 + c];
        }
#pragma unroll
        for (int i=0;i<4;i++) {
            int e = t + i*256;
            int p = e & 127, c = e >> 7;
            Bs[c][p] = in[(size_t)(k0+c)*P + p0 + p];
        }
        __syncthreads();
#pragma unroll
        for (int kk=0; kk<8; kk++) {
            float a[8], bb[8];
#pragma unroll
            for (int i=0;i<8;i++) a[i]  = As[kk][ty*8+i];
#pragma unroll
            for (int j=0;j<8;j++) bb[j] = Bs[kk][tx*8+j];
#pragma unroll
            for (int i=0;i<8;i++)
#pragma unroll
                for (int j=0;j<8;j++)
                    acc[i][j] = fmaf(a[i], bb[j], acc[i][j]);
        }
        __syncthreads();
    }

#pragma unroll
    for (int i=0;i<8;i++) {
        const int o  = o0 + ty*8 + i;
        const float bv = bias ? bias[o] : 0.f;
#pragma unroll
        for (int j=0;j<8;j++) {
            const int p = p0 + tx*8 + j;
            float v = acc[i][j] + bv;
            if (EPI == 1) v = 1.f/(1.f + __expf(-v));
            if (EPI == 2) v = in[(size_t)o*P + p] + v * mask[(size_t)o*P + p];
            out[(size_t)o*P + p] = v;
        }
    }
}

// =====================================================================
// depthwise 3x3 over qkv (384 channels; weight set picked by channel/128)
// =====================================================================
__global__ void dwconv3_k(const float* __restrict__ in,
                          const float* __restrict__ wq,
                          const float* __restrict__ wk,
                          const float* __restrict__ wv,
                          float* __restrict__ out)
{
    const int zc = blockIdx.z;          // b*3C + ch
    const int ch = zc % (3*Cc);
    const int cm = ch % Cc;
    const float* ws = (ch < Cc) ? wq : (ch < 2*Cc ? wk : wv);
    float wgt[9];
#pragma unroll
    for (int i=0;i<9;i++) wgt[i] = ws[cm*9+i];

    const float* ip = in  + (size_t)zc*Nf;
    float*       op = out + (size_t)zc*Nf;

    const int x = blockIdx.x*32 + threadIdx.x;
    const int y = blockIdx.y*8  + threadIdx.y;

    float s = 0.f;
#pragma unroll
    for (int dy=-1; dy<=1; dy++) {
        const int yy = y+dy;
        if (yy < 0 || yy >= Hf) continue;
#pragma unroll
        for (int dx=-1; dx<=1; dx++) {
            const int xx = x+dx;
            if (xx < 0 || xx >= Wf) continue;
            s = fmaf(ip[yy*Wf+xx], wgt[(dy+1)*3+(dx+1)], s);
        }
    }
    op[y*Wf+x] = s;
}

// =====================================================================
// Haar DWT on q (first C channels of qkvd)
// =====================================================================
__global__ void dwt_k(const float* __restrict__ in,
                      float* __restrict__ ll, float* __restrict__ lh,
                      float* __restrict__ hl, float* __restrict__ hh)
{
    const int zc = blockIdx.z;          // b*C + ch
    const int b = zc / Cc, ch = zc % Cc;
    const float* ip = in + ((size_t)b*3*Cc + ch)*Nf;
    const size_t ho = (size_t)zc*Nh2;

    const int x = blockIdx.x*32 + threadIdx.x;   // 0..127
    const int y = blockIdx.y*8  + threadIdx.y;

    const float a  = ip[(2*y)*Wf   + 2*x];
    const float bb = ip[(2*y)*Wf   + 2*x+1];
    const float c  = ip[(2*y+1)*Wf + 2*x];
    const float d  = ip[(2*y+1)*Wf + 2*x+1];
    const int p = y*Wh + x;
    ll[ho+p] = (a+bb+c+d)*0.5f;
    lh[ho+p] = (a+bb-c-d)*0.5f;
    hl[ho+p] = (a-bb+c-d)*0.5f;
    hh[ho+p] = (a-bb-c+d)*0.5f;
}

// =====================================================================
// gated depthwise: out = conv(x,w0) * sigmoid(conv(x,w1)), per channel
// w layout: [branch][C][KH*KW]; w0 at w, w1 at w + C*KH*KW
// =====================================================================
template<int KH,int KW>
__global__ void gated_k(const float* __restrict__ in,
                        const float* __restrict__ w,
                        float* __restrict__ out)
{
    const int zc = blockIdx.z;          // b*C + ch
    const int ch = zc % Cc;
    const float* w0 = w + (size_t)ch*KH*KW;
    const float* w1 = w + (size_t)Cc*KH*KW + (size_t)ch*KH*KW;
    const float* ip = in + (size_t)zc*Nh2;

    const int x = blockIdx.x*32 + threadIdx.x;
    const int y = blockIdx.y*8  + threadIdx.y;

    float s0 = 0.f, s1 = 0.f;
#pragma unroll
    for (int dy=0; dy<KH; dy++) {
        const int yy = y + dy - KH/2;
        if (yy < 0 || yy >= Hh) continue;
#pragma unroll
        for (int dx=0; dx<KW; dx++) {
            const int xx = x + dx - KW/2;
            if (xx < 0 || xx >= Wh) continue;
            const float v = ip[yy*Wh+xx];
            s0 = fmaf(v, w0[dy*KW+dx], s0);
            s1 = fmaf(v, w1[dy*KW+dx], s1);
        }
    }
    out[(size_t)zc*Nh2 + y*Wh + x] = s0 * (1.f/(1.f + __expf(-s1)));
}

// =====================================================================
// inverse DWT with masks applied to lh/hl/hh
// =====================================================================
__global__ void idwt_k(const float* __restrict__ ll, const float* __restrict__ lh,
                       const float* __restrict__ hl, const float* __restrict__ hh,
                       const float* __restrict__ masks, float* __restrict__ out)
{
    const int zc = blockIdx.z;          // b*C + ch
    const int b = zc / Cc, ch = zc % Cc;
    const size_t hp = (size_t)zc*Nh2;
    const float* mb = masks + (size_t)b*5*Cc*Nh2;

    const int x = blockIdx.x*32 + threadIdx.x;
    const int y = blockIdx.y*8  + threadIdx.y;
    const int p = y*Wh + x;

    const float vll = ll[hp+p];
    const float vlh = lh[hp+p] * mb[(size_t)(  Cc+ch)*Nh2 + p];
    const float vhl = hl[hp+p] * mb[(size_t)(2*Cc+ch)*Nh2 + p];
    const float vhh = hh[hp+p] * mb[(size_t)(3*Cc+ch)*Nh2 + p];

    const float a  = (vll+vlh+vhl+vhh)*0.5f;
    const float bb = (vll+vlh-vhl-vhh)*0.5f;
    const float c  = (vll-vlh+vhl-vhh)*0.5f;
    const float d  = (vll-vlh-vhl+vhh)*0.5f;

    float* op = out + (size_t)zc*Nf;
    op[(2*y)*Wf   + 2*x  ] = a;
    op[(2*y)*Wf   + 2*x+1] = bb;
    op[(2*y+1)*Wf + 2*x  ] = c;
    op[(2*y+1)*Wf + 2*x+1] = d;
}

// =====================================================================
// gram pass: per (b,h) accumulate S[i][j]=sum_n q_i k_j, |q_i|^2, |k_j|^2
// q = g_qfull (batch stride C*N), k = g_qkvd + C*N (batch stride 3C*N)
// =====================================================================
#define GRAM_TILES 8
__global__ void __launch_bounds__(256) gram_k(const float* __restrict__ q,
                                              const float* __restrict__ kall,
                                              float* __restrict__ gram)
{
    const int h = blockIdx.y, b = blockIdx.z;
    const float* qb = q    + (size_t)b*Cc*Nf            + (size_t)h*HD*Nf;
    const float* kb = kall + (size_t)b*3*Cc*Nf + (size_t)Cc*Nf + (size_t)h*HD*Nf;

    __shared__ float qs[16][132];
    __shared__ float ks[16][132];

    const int t = threadIdx.x;
    const int i = t >> 4, j = t & 15;
    float accS = 0.f, accQ = 0.f, accK = 0.f;

    const int n0base = blockIdx.x * (GRAM_TILES*128);
    for (int tile=0; tile<GRAM_TILES; tile++) {
        const int n0 = n0base + tile*128;
#pragma unroll
        for (int e=0; e<8; e++) {
            const int idx = t + e*256;
            const int r = idx >> 7, c = idx & 127;
            qs[r][c] = qb[(size_t)r*Nf + n0 + c];
            ks[r][c] = kb[(size_t)r*Nf + n0 + c];
        }
        __syncthreads();
#pragma unroll 8
        for (int nn=0; nn<128; nn++) {
            const float qv = qs[i][nn];
            const float kv = ks[j][nn];
            accS = fmaf(qv, kv, accS);
            if (j == 0) accQ = fmaf(qv, qv, accQ);
            if (i == 0) accK = fmaf(kv, kv, accK);
        }
        __syncthreads();
    }
    float* gp = gram + (size_t)(b*NHh + h)*288;
    atomicAdd(gp + i*16 + j, accS);
    if (j == 0) atomicAdd(gp + 256 + i, accQ);
    if (i == 0) atomicAdd(gp + 272 + j, accK);
}

// =====================================================================
// softmax + fold w_out: Weff_b = w_out @ blockdiag(att_b)
// =====================================================================
__global__ void attw_k(const float* __restrict__ gram,
                       const float* __restrict__ temp,
                       const float* __restrict__ wout,
                       float* __restrict__ weff)
{
    const int b = blockIdx.x;
    __shared__ float att[NHh][16][16];
    const int t = threadIdx.x;          // 256 threads
    const float* gb = gram + (size_t)b*NHh*288;

    if (t < 128) {
        const int h = t >> 4, i = t & 15;
        const float* gp = gb + h*288;
        const float nq = fmaxf(sqrtf(gp[256+i]), 1e-12f);
        const float tv = temp[h];
        float logit[16];
        float mx = -1e30f;
#pragma unroll
        for (int j=0;j<16;j++) {
            const float nk = fmaxf(sqrtf(gp[272+j]), 1e-12f);
            const float l = gp[i*16+j] / (nq*nk) * tv;
            logit[j] = l;
            mx = fmaxf(mx, l);
        }
        float se = 0.f;
#pragma unroll
        for (int j=0;j<16;j++) { const float e = __expf(logit[j]-mx); logit[j]=e; se+=e; }
        const float inv = 1.f/se;
#pragma unroll
        for (int j=0;j<16;j++) att[h][i][j] = logit[j]*inv;
    }
    __syncthreads();

    float* wb = weff + (size_t)b*Cc*Cc;
    for (int idx = t; idx < Cc*Cc; idx += 256) {
        const int o = idx >> 7, cp = idx & 127;
        const int h = cp >> 4, j = cp & 15;
        float s = 0.f;
#pragma unroll
        for (int i=0;i<16;i++)
            s = fmaf(wout[(size_t)o*Cc + h*16 + i], att[h][i][j], s);
        wb[idx] = s;
    }
}

// =====================================================================
// host launch
// =====================================================================
extern "C" void kernel_launch(void* const* d_in, const int* in_sizes, int n_in,
                              void* d_out, int out_size)
{
    const float* x      = (const float*)d_in[0];
    const float* prior  = (const float*)d_in[1];
    const float* w_lin  = (const float*)d_in[2];
    const float* b_lin  = (const float*)d_in[3];
    const float* w_qd   = (const float*)d_in[4];
    const float* w_kd   = (const float*)d_in[5];
    const float* w_vd   = (const float*)d_in[6];
    const float* gw_llr = (const float*)d_in[7];
    const float* gw_llh = (const float*)d_in[8];
    const float* gw_lh  = (const float*)d_in[9];
    const float* gw_hl  = (const float*)d_in[10];
    const float* gw_hh  = (const float*)d_in[11];
    const float* w_prior= (const float*)d_in[12];
    const float* b_prior= (const float*)d_in[13];
    const float* w_pw1  = (const float*)d_in[14];
    const float* b_pw1  = (const float*)d_in[15];
    const float* w_pw2  = (const float*)d_in[16];
    const float* b_pw2  = (const float*)d_in[17];
    const float* w_cat  = (const float*)d_in[18];
    const float* b_cat  = (const float*)d_in[19];
    const float* temper = (const float*)d_in[20];
    const float* w_out  = (const float*)d_in[21];
    const float* b_out  = (const float*)d_in[22];

    float *qkv, *qkvd, *hbuf, *masks, *qcat, *qfull, *gram, *weff;
    cudaGetSymbolAddress((void**)&qkv,   g_qkv);
    cudaGetSymbolAddress((void**)&qkvd,  g_qkvd);
    cudaGetSymbolAddress((void**)&hbuf,  g_hbuf);
    cudaGetSymbolAddress((void**)&masks, g_masks);
    cudaGetSymbolAddress((void**)&qcat,  g_qcat);
    cudaGetSymbolAddress((void**)&qfull, g_qfull);
    cudaGetSymbolAddress((void**)&gram,  g_gram);
    cudaGetSymbolAddress((void**)&weff,  g_weff);

    float* ll   = hbuf + 0*HB;
    float* lh   = hbuf + 1*HB;
    float* hl   = hbuf + 2*HB;
    float* hh   = hbuf + 3*HB;
    float* tA   = hbuf + 4*HB;
    float* llrg = hbuf + 5*HB;
    float* llhg = hbuf + 6*HB;
    float* lhg  = hbuf + 7*HB;
    float* hlg  = hbuf + 8*HB;
    float* hhg  = hbuf + 9*HB;

    const size_t fullBS = (size_t)Cc*Nf;        // (B,C,H,W) batch stride
    const size_t qkvBS  = (size_t)3*Cc*Nf;
    const size_t halfBS = (size_t)Cc*Nh2;
    const size_t mBS    = (size_t)5*Cc*Nh2;
    const size_t catBS  = (size_t)2*Cc*Nh2;

    // 1. qkv = conv1x1(x, w_lin) + b_lin
    conv1x1_k<0><<<dim3(Nf/128, 384/128, Bq), 256>>>(
        x, w_lin, b_lin, qkv, nullptr, Cc, Nf, fullBS, qkvBS, 0, 0);

    // 2. depthwise 3x3 on q,k,v
    dwconv3_k<<<dim3(Wf/32, Hf/8, Bq*3*Cc), dim3(32,8)>>>(qkv, w_qd, w_kd, w_vd, qkvd);

    // 3. Haar DWT on q
    dim3 gh(Wh/32, Hh/8, Bq*Cc), bh(32,8);
    dwt_k<<<gh, bh>>>(qkvd, ll, lh, hl, hh);

    // 4. gated depthwise chains  (g_llr/g_llh layout: [d][branch][C][kh*kw])
    gated_k<3,3><<<gh, bh>>>(ll, gw_llr,             tA);
    gated_k<3,3><<<gh, bh>>>(tA, gw_llr + 2*Cc*9,    llrg);
    gated_k<3,3><<<gh, bh>>>(ll, gw_llh,             tA);
    gated_k<3,3><<<gh, bh>>>(tA, gw_llh + 2*Cc*9,    llhg);
    gated_k<3,5><<<gh, bh>>>(lh, gw_lh,              lhg);
    gated_k<5,3><<<gh, bh>>>(hl, gw_hl,              hlg);
    gated_k<3,3><<<gh, bh>>>(hh, gw_hh,              hhg);

    // 5. masks = sigmoid(conv1x1(prior, w_prior))
    conv1x1_k<1><<<dim3(Nh2/128, 640/128, Bq), 256>>>(
        prior, w_prior, b_prior, masks, nullptr, Cc, Nh2, halfBS, mBS, 0, 0);

    // 6. pw residual-mask blocks -> concatenated buffer qcat
    conv1x1_k<2><<<dim3(Nh2/128, 1, Bq), 256>>>(
        llrg, w_pw1, b_pw1, qcat, masks /*m_ll*/, Cc, Nh2,
        halfBS, catBS, 0, mBS);
    conv1x1_k<2><<<dim3(Nh2/128, 1, Bq), 256>>>(
        llhg, w_pw2, b_pw2, qcat + (size_t)Cc*Nh2, masks + (size_t)4*Cc*Nh2 /*m_hp*/, Cc, Nh2,
        halfBS, catBS, 0, mBS);

    // 7. q_ll = conv1x1(cat, w_cat) + b_cat    (reuse ll buffer)
    conv1x1_k<0><<<dim3(Nh2/128, 1, Bq), 256>>>(
        qcat, w_cat, b_cat, ll, nullptr, 2*Cc, Nh2, catBS, halfBS, 0, 0);

    // 8. inverse DWT with m_lh/m_hl/m_hh applied
    idwt_k<<<gh, bh>>>(ll, lhg, hlg, hhg, masks, qfull);

    // 9. gram matrices + norms
    cudaMemsetAsync(gram, 0, (size_t)Bq*NHh*288*sizeof(float));
    gram_k<<<dim3(Nf/(GRAM_TILES*128), NHh, Bq), 256>>>(qfull, qkvd, gram);

    // 10. softmax + fold into Weff = w_out @ blockdiag(att)
    attw_k<<<Bq, 256>>>(gram, temper, w_out, weff);

    // 11. final: out = Weff_b @ v + b_out   (v = qkvd channels [2C,3C))
    conv1x1_k<0><<<dim3(Nf/128, 1, Bq), 256>>>(
        qkvd + (size_t)2*Cc*Nf, weff, b_out, (float*)d_out, nullptr, Cc, Nf,
        qkvBS, fullBS, (size_t)Cc*Cc, 0);

    // 12. second output = prior (pass-through), concatenated after first output
    const size_t xel = (size_t)in_sizes[0];
    const size_t pel = (size_t)in_sizes[1];
    if ((size_t)out_size >= xel + pel) {
        cudaMemcpyAsync((float*)d_out + xel, prior, pel*sizeof(float),
                        cudaMemcpyDeviceToDevice);
    }
}

// round 3
// speedup vs baseline: 2.1901x; 2.1901x over previous
#include <cuda_runtime.h>
#include <cuda_bf16.h>
#include <cstdint>
#include <math.h>

// ---------------- problem constants ----------------
#define Bq   2
#define Cc   128
#define Hf   256
#define Wf   256
#define Nf   (Hf*Wf)      // 65536
#define Hh   128
#define Wh   128
#define Nh2  (Hh*Wh)      // 16384
#define NHh  8
#define HD   16

#define HB   ((size_t)Bq*Cc*Nh2)

// ---------------- device scratch ----------------
__device__ float g_qkv [(size_t)Bq*3*Cc*Nf];
__device__ float g_qkvd[(size_t)Bq*3*Cc*Nf];
__device__ float g_hbuf[10*((size_t)Bq*Cc*Nh2)];
__device__ float g_masks[(size_t)Bq*5*Cc*Nh2];
__device__ float g_qcat [(size_t)Bq*2*Cc*Nh2];
__device__ float g_qfull[(size_t)Bq*Cc*Nf];
__device__ float g_gram [Bq*NHh*288];
__device__ float g_weff [Bq*Cc*Cc];

// =====================================================================
// tf32 helpers
// =====================================================================
__device__ __forceinline__ uint32_t f2tf32(float f) {
    uint32_t r;
    asm("cvt.rna.tf32.f32 %0, %1;" : "=r"(r) : "f"(f));
    return r;
}
__device__ __forceinline__ void mma_tf32(float c[4], const uint32_t a[4], const uint32_t b[2]) {
    asm volatile(
        "mma.sync.aligned.m16n8k8.row.col.f32.tf32.tf32.f32 "
        "{%0,%1,%2,%3}, {%4,%5,%6,%7}, {%8,%9}, {%0,%1,%2,%3};"
        : "+f"(c[0]), "+f"(c[1]), "+f"(c[2]), "+f"(c[3])
        : "r"(a[0]), "r"(a[1]), "r"(a[2]), "r"(a[3]), "r"(b[0]), "r"(b[1]));
}

// =====================================================================
// conv1x1 as tf32 tensor-core GEMM:
//   out[o,p] = epi( sum_c W[o,c] * in[c,p] + bias[o] )
// Block: 256 thr (8 warps, 4x2). Tile BM=128 (o), BN=128 (p), BK=32.
// Warp tile 32(o) x 64(p): 2 m16 x 8 n8 mma tiles.
// EPI: 0=bias, 1=sigmoid, 2=residual+mask
// =====================================================================
#define A_STR 36
#define B_STR 132

template<int EPI>
__global__ void __launch_bounds__(256) conv1x1_mma(
    const float* __restrict__ in, const float* __restrict__ w,
    const float* __restrict__ bias, float* __restrict__ out,
    const float* __restrict__ mask,
    int Cin, int P,
    size_t inBS, size_t outBS, size_t wBS, size_t maskBS)
{
    const int b = blockIdx.z;
    in  += (size_t)b * inBS;
    out += (size_t)b * outBS;
    w   += (size_t)b * wBS;
    if (EPI == 2) mask += (size_t)b * maskBS;

    const int p0 = blockIdx.x * 128;
    const int o0 = blockIdx.y * 128;

    __shared__ uint32_t As[128 * A_STR];   // [o][k], tf32
    __shared__ uint32_t Bs[32 * B_STR];    // [k][p], tf32

    const int t = threadIdx.x;
    const int lane = t & 31;
    const int wrp  = t >> 5;
    const int wm   = wrp & 3;              // 0..3  -> o rows [wm*32, +32)
    const int wn   = wrp >> 2;             // 0..1  -> p cols [wn*64, +64)
    const int gid  = lane >> 2;            // groupID 0..7
    const int tig  = lane & 3;             // threadInGroup 0..3

    float acc[2][8][4];
#pragma unroll
    for (int i = 0; i < 2; i++)
#pragma unroll
        for (int j = 0; j < 8; j++)
#pragma unroll
            for (int r = 0; r < 4; r++) acc[i][j][r] = 0.f;

    const int nStages = Cin >> 5;
    for (int stage = 0; stage < nStages; stage++) {
        const int cbase = stage << 5;

        // ---- stage A: W[o0+o][cbase + 0..31] -> As[o][k]
        {
            const float* wb = w + (size_t)o0 * Cin + cbase;
#pragma unroll
            for (int i = 0; i < 4; i++) {
                const int slot = t + i * 256;       // 1024 float4 slots
                const int o  = slot >> 3;
                const int c4 = slot & 7;
                const float4 v = *(const float4*)(wb + (size_t)o * Cin + c4 * 4);
                uint32_t* dst = As + o * A_STR + c4 * 4;
                dst[0] = f2tf32(v.x); dst[1] = f2tf32(v.y);
                dst[2] = f2tf32(v.z); dst[3] = f2tf32(v.w);
            }
        }
        // ---- stage B: in[cbase+c][p0 + 0..127] -> Bs[c][p]
        {
            const float* ib = in + (size_t)cbase * P + p0;
#pragma unroll
            for (int i = 0; i < 4; i++) {
                const int slot = t + i * 256;       // 1024 float4 slots
                const int c  = slot >> 5;
                const int p4 = slot & 31;
                const float4 v = *(const float4*)(ib + (size_t)c * P + p4 * 4);
                uint32_t* dst = Bs + c * B_STR + p4 * 4;
                dst[0] = f2tf32(v.x); dst[1] = f2tf32(v.y);
                dst[2] = f2tf32(v.z); dst[3] = f2tf32(v.w);
            }
        }
        __syncthreads();

#pragma unroll
        for (int k0 = 0; k0 < 32; k0 += 8) {
            uint32_t af[2][4];
#pragma unroll
            for (int tm = 0; tm < 2; tm++) {
                const int rb = wm * 32 + tm * 16;
                af[tm][0] = As[(rb + gid    ) * A_STR + k0 + tig    ];
                af[tm][1] = As[(rb + gid + 8) * A_STR + k0 + tig    ];
                af[tm][2] = As[(rb + gid    ) * A_STR + k0 + tig + 4];
                af[tm][3] = As[(rb + gid + 8) * A_STR + k0 + tig + 4];
            }
#pragma unroll
            for (int tn = 0; tn < 8; tn++) {
                uint32_t bf[2];
                const int col = wn * 64 + tn * 8 + gid;
                bf[0] = Bs[(k0 + tig    ) * B_STR + col];
                bf[1] = Bs[(k0 + tig + 4) * B_STR + col];
#pragma unroll
                for (int tm = 0; tm < 2; tm++)
                    mma_tf32(acc[tm][tn], af[tm], bf);
            }
        }
        __syncthreads();
    }

    // ---- epilogue
#pragma unroll
    for (int tm = 0; tm < 2; tm++) {
        const int oA = o0 + wm * 32 + tm * 16 + gid;
        const int oB = oA + 8;
        const float bvA = __ldg(bias + oA);
        const float bvB = __ldg(bias + oB);
#pragma unroll
        for (int tn = 0; tn < 8; tn++) {
            const int p = p0 + wn * 64 + tn * 8 + tig * 2;
            float v0 = acc[tm][tn][0] + bvA;
            float v1 = acc[tm][tn][1] + bvA;
            float v2 = acc[tm][tn][2] + bvB;
            float v3 = acc[tm][tn][3] + bvB;
            if (EPI == 1) {
                v0 = 1.f/(1.f+__expf(-v0)); v1 = 1.f/(1.f+__expf(-v1));
                v2 = 1.f/(1.f+__expf(-v2)); v3 = 1.f/(1.f+__expf(-v3));
            }
            if (EPI == 2) {
                const float2 iA = *(const float2*)(in + (size_t)oA * P + p);
                const float2 iB = *(const float2*)(in + (size_t)oB * P + p);
                const float2 mA = *(const float2*)(mask + (size_t)oA * P + p);
                const float2 mB = *(const float2*)(mask + (size_t)oB * P + p);
                v0 = iA.x + v0 * mA.x; v1 = iA.y + v1 * mA.y;
                v2 = iB.x + v2 * mB.x; v3 = iB.y + v3 * mB.y;
            }
            *(float2*)(out + (size_t)oA * P + p) = make_float2(v0, v1);
            *(float2*)(out + (size_t)oB * P + p) = make_float2(v2, v3);
        }
    }
}

// =====================================================================
// depthwise 3x3 over qkv, 4 px/thread
// =====================================================================
__global__ void __launch_bounds__(256) dwconv3_k(
    const float* __restrict__ in, const float* __restrict__ wq,
    const float* __restrict__ wk, const float* __restrict__ wv,
    float* __restrict__ out)
{
    const int zc = blockIdx.z;
    const int ch = zc % (3*Cc);
    const int cm = ch % Cc;
    const float* ws = (ch < Cc) ? wq : (ch < 2*Cc ? wk : wv);
    float wgt[9];
#pragma unroll
    for (int i=0;i<9;i++) wgt[i] = __ldg(ws + cm*9 + i);

    const float* ip = in  + (size_t)zc*Nf;
    float*       op = out + (size_t)zc*Nf;

    const int x0 = (blockIdx.x*32 + threadIdx.x)*4;
    const int y  = blockIdx.y*8  + threadIdx.y;

    float r[3][6];
#pragma unroll
    for (int dy=0; dy<3; dy++) {
        const int yy = y + dy - 1;
        const bool rv = (unsigned)yy < (unsigned)Hf;
        const float* rp = ip + (size_t)yy*Wf;
#pragma unroll
        for (int j=0; j<6; j++) {
            const int xx = x0 + j - 1;
            r[dy][j] = (rv && (unsigned)xx < (unsigned)Wf) ? __ldg(rp + xx) : 0.f;
        }
    }
    float o[4] = {0.f,0.f,0.f,0.f};
#pragma unroll
    for (int dy=0; dy<3; dy++)
#pragma unroll
        for (int dx=0; dx<3; dx++) {
            const float wv_ = wgt[dy*3+dx];
#pragma unroll
            for (int j=0; j<4; j++) o[j] = fmaf(r[dy][j+dx], wv_, o[j]);
        }
    *(float4*)(op + (size_t)y*Wf + x0) = make_float4(o[0],o[1],o[2],o[3]);
}

// =====================================================================
// Haar DWT, 2 px/thread
// =====================================================================
__global__ void __launch_bounds__(256) dwt_k(
    const float* __restrict__ in,
    float* __restrict__ ll, float* __restrict__ lh,
    float* __restrict__ hl, float* __restrict__ hh)
{
    const int zc = blockIdx.z;
    const int b = zc / Cc, ch = zc % Cc;
    const float* ip = in + ((size_t)b*3*Cc + ch)*Nf;
    const size_t ho = (size_t)zc*Nh2;

    const int x0 = (blockIdx.x*32 + threadIdx.x)*2;
    const int y  = blockIdx.y*8  + threadIdx.y;

    const float4 r0 = *(const float4*)(ip + (size_t)(2*y)*Wf   + 2*x0);
    const float4 r1 = *(const float4*)(ip + (size_t)(2*y+1)*Wf + 2*x0);
    const size_t p = ho + (size_t)y*Wh + x0;
    *(float2*)(ll+p) = make_float2((r0.x+r0.y+r1.x+r1.y)*0.5f, (r0.z+r0.w+r1.z+r1.w)*0.5f);
    *(float2*)(lh+p) = make_float2((r0.x+r0.y-r1.x-r1.y)*0.5f, (r0.z+r0.w-r1.z-r1.w)*0.5f);
    *(float2*)(hl+p) = make_float2((r0.x-r0.y+r1.x-r1.y)*0.5f, (r0.z-r0.w+r1.z-r1.w)*0.5f);
    *(float2*)(hh+p) = make_float2((r0.x-r0.y-r1.x+r1.y)*0.5f, (r0.z-r0.w-r1.z+r1.w)*0.5f);
}

// =====================================================================
// gated depthwise, 4 px/thread
// =====================================================================
template<int KH,int KW>
__global__ void __launch_bounds__(256) gated_k(
    const float* __restrict__ in, const float* __restrict__ w,
    float* __restrict__ out)
{
    const int zc = blockIdx.z;
    const int ch = zc % Cc;
    const float* w0 = w + (size_t)ch*KH*KW;
    const float* w1 = w + (size_t)Cc*KH*KW + (size_t)ch*KH*KW;
    float wv0[KH*KW], wv1[KH*KW];
#pragma unroll
    for (int i=0;i<KH*KW;i++) { wv0[i] = __ldg(w0+i); wv1[i] = __ldg(w1+i); }

    const float* ip = in + (size_t)zc*Nh2;
    const int x0 = (blockIdx.x*32 + threadIdx.x)*4;
    const int y  = blockIdx.y*8  + threadIdx.y;
    constexpr int W4 = KW + 3;

    float r[KH][W4];
#pragma unroll
    for (int ky=0; ky<KH; ky++) {
        const int yy = y + ky - KH/2;
        const bool rv = (unsigned)yy < (unsigned)Hh;
        const float* rp = ip + (size_t)yy*Wh;
#pragma unroll
        for (int j=0; j<W4; j++) {
            const int xx = x0 + j - KW/2;
            r[ky][j] = (rv && (unsigned)xx < (unsigned)Wh) ? __ldg(rp + xx) : 0.f;
        }
    }
    float s0[4] = {0,0,0,0}, s1[4] = {0,0,0,0};
#pragma unroll
    for (int ky=0; ky<KH; ky++)
#pragma unroll
        for (int kx=0; kx<KW; kx++) {
            const float a0 = wv0[ky*KW+kx], a1 = wv1[ky*KW+kx];
#pragma unroll
            for (int j=0; j<4; j++) {
                s0[j] = fmaf(r[ky][j+kx], a0, s0[j]);
                s1[j] = fmaf(r[ky][j+kx], a1, s1[j]);
            }
        }
    float4 o;
    o.x = s0[0] * (1.f/(1.f+__expf(-s1[0])));
    o.y = s0[1] * (1.f/(1.f+__expf(-s1[1])));
    o.z = s0[2] * (1.f/(1.f+__expf(-s1[2])));
    o.w = s0[3] * (1.f/(1.f+__expf(-s1[3])));
    *(float4*)(out + (size_t)zc*Nh2 + (size_t)y*Wh + x0) = o;
}

// =====================================================================
// inverse DWT with masks, 2 px/thread
// =====================================================================
__global__ void __launch_bounds__(256) idwt_k(
    const float* __restrict__ ll, const float* __restrict__ lh,
    const float* __restrict__ hl, const float* __restrict__ hh,
    const float* __restrict__ masks, float* __restrict__ out)
{
    const int zc = blockIdx.z;
    const int b = zc / Cc, ch = zc % Cc;
    const size_t hp = (size_t)zc*Nh2;
    const float* mb = masks + (size_t)b*5*Cc*Nh2;

    const int x0 = (blockIdx.x*32 + threadIdx.x)*2;
    const int y  = blockIdx.y*8  + threadIdx.y;
    const size_t p = (size_t)y*Wh + x0;

    const float2 vll = *(const float2*)(ll+hp+p);
    float2 vlh = *(const float2*)(lh+hp+p);
    float2 vhl = *(const float2*)(hl+hp+p);
    float2 vhh = *(const float2*)(hh+hp+p);
    const float2 m1 = *(const float2*)(mb + (size_t)(  Cc+ch)*Nh2 + p);
    const float2 m2 = *(const float2*)(mb + (size_t)(2*Cc+ch)*Nh2 + p);
    const float2 m3 = *(const float2*)(mb + (size_t)(3*Cc+ch)*Nh2 + p);
    vlh.x *= m1.x; vlh.y *= m1.y;
    vhl.x *= m2.x; vhl.y *= m2.y;
    vhh.x *= m3.x; vhh.y *= m3.y;

    float* op = out + (size_t)zc*Nf;
    float4 t0, t1;
    t0.x = (vll.x+vlh.x+vhl.x+vhh.x)*0.5f;
    t0.y = (vll.x+vlh.x-vhl.x-vhh.x)*0.5f;
    t0.z = (vll.y+vlh.y+vhl.y+vhh.y)*0.5f;
    t0.w = (vll.y+vlh.y-vhl.y-vhh.y)*0.5f;
    t1.x = (vll.x-vlh.x+vhl.x-vhh.x)*0.5f;
    t1.y = (vll.x-vlh.x-vhl.x+vhh.x)*0.5f;
    t1.z = (vll.y-vlh.y+vhl.y-vhh.y)*0.5f;
    t1.w = (vll.y-vlh.y-vhl.y+vhh.y)*0.5f;
    *(float4*)(op + (size_t)(2*y)*Wf   + 2*x0) = t0;
    *(float4*)(op + (size_t)(2*y+1)*Wf + 2*x0) = t1;
}

// =====================================================================
// gram pass
// =====================================================================
#define GRAM_TILES 8
__global__ void __launch_bounds__(256) gram_k(const float* __restrict__ q,
                                              const float* __restrict__ kall,
                                              float* __restrict__ gram)
{
    const int h = blockIdx.y, b = blockIdx.z;
    const float* qb = q    + (size_t)b*Cc*Nf            + (size_t)h*HD*Nf;
    const float* kb = kall + (size_t)b*3*Cc*Nf + (size_t)Cc*Nf + (size_t)h*HD*Nf;

    __shared__ float qs[16][132];
    __shared__ float ks[16][132];

    const int t = threadIdx.x;
    const int i = t >> 4, j = t & 15;
    float accS = 0.f, accQ = 0.f, accK = 0.f;

    const int n0base = blockIdx.x * (GRAM_TILES*128);
    for (int tile=0; tile<GRAM_TILES; tile++) {
        const int n0 = n0base + tile*128;
#pragma unroll
        for (int e=0; e<8; e++) {
            const int idx = t + e*256;
            const int r = idx >> 7, c = idx & 127;
            qs[r][c] = qb[(size_t)r*Nf + n0 + c];
            ks[r][c] = kb[(size_t)r*Nf + n0 + c];
        }
        __syncthreads();
#pragma unroll 8
        for (int nn=0; nn<128; nn++) {
            const float qv = qs[i][nn];
            const float kv = ks[j][nn];
            accS = fmaf(qv, kv, accS);
            if (j == 0) accQ = fmaf(qv, qv, accQ);
            if (i == 0) accK = fmaf(kv, kv, accK);
        }
        __syncthreads();
    }
    float* gp = gram + (size_t)(b*NHh + h)*288;
    atomicAdd(gp + i*16 + j, accS);
    if (j == 0) atomicAdd(gp + 256 + i, accQ);
    if (i == 0) atomicAdd(gp + 272 + j, accK);
}

// =====================================================================
// softmax + fold w_out
// =====================================================================
__global__ void attw_k(const float* __restrict__ gram,
                       const float* __restrict__ temp,
                       const float* __restrict__ wout,
                       float* __restrict__ weff)
{
    const int b = blockIdx.x;
    __shared__ float att[NHh][16][16];
    const int t = threadIdx.x;
    const float* gb = gram + (size_t)b*NHh*288;

    if (t < 128) {
        const int h = t >> 4, i = t & 15;
        const float* gp = gb + h*288;
        const float nq = fmaxf(sqrtf(gp[256+i]), 1e-12f);
        const float tv = temp[h];
        float logit[16];
        float mx = -1e30f;
#pragma unroll
        for (int j=0;j<16;j++) {
            const float nk = fmaxf(sqrtf(gp[272+j]), 1e-12f);
            const float l = gp[i*16+j] / (nq*nk) * tv;
            logit[j] = l;
            mx = fmaxf(mx, l);
        }
        float se = 0.f;
#pragma unroll
        for (int j=0;j<16;j++) { const float e = __expf(logit[j]-mx); logit[j]=e; se+=e; }
        const float inv = 1.f/se;
#pragma unroll
        for (int j=0;j<16;j++) att[h][i][j] = logit[j]*inv;
    }
    __syncthreads();

    float* wb = weff + (size_t)b*Cc*Cc;
    for (int idx = t; idx < Cc*Cc; idx += 256) {
        const int o = idx >> 7, cp = idx & 127;
        const int h = cp >> 4, j = cp & 15;
        float s = 0.f;
#pragma unroll
        for (int i=0;i<16;i++)
            s = fmaf(wout[(size_t)o*Cc + h*16 + i], att[h][i][j], s);
        wb[idx] = s;
    }
}

// =====================================================================
// host launch
// =====================================================================
extern "C" void kernel_launch(void* const* d_in, const int* in_sizes, int n_in,
                              void* d_out, int out_size)
{
    const float* x      = (const float*)d_in[0];
    const float* prior  = (const float*)d_in[1];
    const float* w_lin  = (const float*)d_in[2];
    const float* b_lin  = (const float*)d_in[3];
    const float* w_qd   = (const float*)d_in[4];
    const float* w_kd   = (const float*)d_in[5];
    const float* w_vd   = (const float*)d_in[6];
    const float* gw_llr = (const float*)d_in[7];
    const float* gw_llh = (const float*)d_in[8];
    const float* gw_lh  = (const float*)d_in[9];
    const float* gw_hl  = (const float*)d_in[10];
    const float* gw_hh  = (const float*)d_in[11];
    const float* w_prior= (const float*)d_in[12];
    const float* b_prior= (const float*)d_in[13];
    const float* w_pw1  = (const float*)d_in[14];
    const float* b_pw1  = (const float*)d_in[15];
    const float* w_pw2  = (const float*)d_in[16];
    const float* b_pw2  = (const float*)d_in[17];
    const float* w_cat  = (const float*)d_in[18];
    const float* b_cat  = (const float*)d_in[19];
    const float* temper = (const float*)d_in[20];
    const float* w_out  = (const float*)d_in[21];
    const float* b_out  = (const float*)d_in[22];

    float *qkv, *qkvd, *hbuf, *masks, *qcat, *qfull, *gram, *weff;
    cudaGetSymbolAddress((void**)&qkv,   g_qkv);
    cudaGetSymbolAddress((void**)&qkvd,  g_qkvd);
    cudaGetSymbolAddress((void**)&hbuf,  g_hbuf);
    cudaGetSymbolAddress((void**)&masks, g_masks);
    cudaGetSymbolAddress((void**)&qcat,  g_qcat);
    cudaGetSymbolAddress((void**)&qfull, g_qfull);
    cudaGetSymbolAddress((void**)&gram,  g_gram);
    cudaGetSymbolAddress((void**)&weff,  g_weff);

    float* ll   = hbuf + 0*HB;
    float* lh   = hbuf + 1*HB;
    float* hl   = hbuf + 2*HB;
    float* hh   = hbuf + 3*HB;
    float* tA   = hbuf + 4*HB;
    float* llrg = hbuf + 5*HB;
    float* llhg = hbuf + 6*HB;
    float* lhg  = hbuf + 7*HB;
    float* hlg  = hbuf + 8*HB;
    float* hhg  = hbuf + 9*HB;

    const size_t fullBS = (size_t)Cc*Nf;
    const size_t qkvBS  = (size_t)3*Cc*Nf;
    const size_t halfBS = (size_t)Cc*Nh2;
    const size_t mBS    = (size_t)5*Cc*Nh2;
    const size_t catBS  = (size_t)2*Cc*Nh2;

    // 1. qkv = conv1x1(x, w_lin) + b_lin
    conv1x1_mma<0><<<dim3(Nf/128, 3, Bq), 256>>>(
        x, w_lin, b_lin, qkv, nullptr, Cc, Nf, fullBS, qkvBS, 0, 0);

    // 2. depthwise 3x3 on q,k,v
    dwconv3_k<<<dim3(Wf/128, Hf/8, Bq*3*Cc), dim3(32,8)>>>(qkv, w_qd, w_kd, w_vd, qkvd);

    // 3. Haar DWT on q
    dwt_k<<<dim3(Wh/64, Hh/8, Bq*Cc), dim3(32,8)>>>(qkvd, ll, lh, hl, hh);

    // 4. gated depthwise chains
    dim3 gg(Wh/128, Hh/8, Bq*Cc), bg(32,8);
    gated_k<3,3><<<gg, bg>>>(ll, gw_llr,          tA);
    gated_k<3,3><<<gg, bg>>>(tA, gw_llr + 2*Cc*9, llrg);
    gated_k<3,3><<<gg, bg>>>(ll, gw_llh,          tA);
    gated_k<3,3><<<gg, bg>>>(tA, gw_llh + 2*Cc*9, llhg);
    gated_k<3,5><<<gg, bg>>>(lh, gw_lh,           lhg);
    gated_k<5,3><<<gg, bg>>>(hl, gw_hl,           hlg);
    gated_k<3,3><<<gg, bg>>>(hh, gw_hh,           hhg);

    // 5. masks = sigmoid(conv1x1(prior, w_prior))
    conv1x1_mma<1><<<dim3(Nh2/128, 5, Bq), 256>>>(
        prior, w_prior, b_prior, masks, nullptr, Cc, Nh2, halfBS, mBS, 0, 0);

    // 6. pw residual-mask blocks -> qcat
    conv1x1_mma<2><<<dim3(Nh2/128, 1, Bq), 256>>>(
        llrg, w_pw1, b_pw1, qcat, masks, Cc, Nh2, halfBS, catBS, 0, mBS);
    conv1x1_mma<2><<<dim3(Nh2/128, 1, Bq), 256>>>(
        llhg, w_pw2, b_pw2, qcat + (size_t)Cc*Nh2, masks + (size_t)4*Cc*Nh2, Cc, Nh2,
        halfBS, catBS, 0, mBS);

    // 7. q_ll = conv1x1(cat, w_cat) + b_cat  (Cin=256)
    conv1x1_mma<0><<<dim3(Nh2/128, 1, Bq), 256>>>(
        qcat, w_cat, b_cat, ll, nullptr, 2*Cc, Nh2, catBS, halfBS, 0, 0);

    // 8. inverse DWT with masks
    idwt_k<<<dim3(Wh/64, Hh/8, Bq*Cc), dim3(32,8)>>>(ll, lhg, hlg, hhg, masks, qfull);

    // 9. gram matrices + norms
    cudaMemsetAsync(gram, 0, (size_t)Bq*NHh*288*sizeof(float));
    gram_k<<<dim3(Nf/(GRAM_TILES*128), NHh, Bq), 256>>>(qfull, qkvd, gram);

    // 10. softmax + fold into Weff
    attw_k<<<Bq, 256>>>(gram, temper, w_out, weff);

    // 11. final: out = Weff_b @ v + b_out
    conv1x1_mma<0><<<dim3(Nf/128, 1, Bq), 256>>>(
        qkvd + (size_t)2*Cc*Nf, weff, b_out, (float*)d_out, nullptr, Cc, Nf,
        qkvBS, fullBS, (size_t)Cc*Cc, 0);

    // 12. second output = prior pass-through
    const size_t xel = (size_t)in_sizes[0];
    const size_t pel = (size_t)in_sizes[1];
    if ((size_t)out_size >= xel + pel) {
        cudaMemcpyAsync((float*)d_out + xel, prior, pel*sizeof(float),
                        cudaMemcpyDeviceToDevice);
    }
}

// round 5
// speedup vs baseline: 2.3545x; 1.0751x over previous
#include <cuda_runtime.h>
#include <cuda_bf16.h>
#include <cstdint>
#include <math.h>

// ---------------- problem constants ----------------
#define Bq   2
#define Cc   128
#define Hf   256
#define Wf   256
#define Nf   (Hf*Wf)      // 65536
#define Hh   128
#define Wh   128
#define Nh2  (Hh*Wh)      // 16384
#define NHh  8
#define HD   16

#define HB   ((size_t)Bq*Cc*Nh2)

// ---------------- device scratch ----------------
__device__ float g_qkv [(size_t)Bq*3*Cc*Nf];
__device__ float g_qkvd[(size_t)Bq*3*Cc*Nf];
__device__ float g_hbuf[10*((size_t)Bq*Cc*Nh2)];
__device__ float g_masks[(size_t)Bq*5*Cc*Nh2];
__device__ float g_qcat [(size_t)Bq*2*Cc*Nh2];
__device__ float g_qfull[(size_t)Bq*Cc*Nf];
__device__ float g_gram [Bq*NHh*288];
__device__ float g_weff [Bq*Cc*Cc];

__device__ __forceinline__ float sigm(float v) { return 1.f/(1.f+__expf(-v)); }

// =====================================================================
// tf32 helpers
// =====================================================================
__device__ __forceinline__ uint32_t f2tf32(float f) {
    uint32_t r;
    asm("cvt.rna.tf32.f32 %0, %1;" : "=r"(r) : "f"(f));
    return r;
}
__device__ __forceinline__ void mma_tf32(float c[4], const uint32_t a[4], const uint32_t b[2]) {
    asm volatile(
        "mma.sync.aligned.m16n8k8.row.col.f32.tf32.tf32.f32 "
        "{%0,%1,%2,%3}, {%4,%5,%6,%7}, {%8,%9}, {%0,%1,%2,%3};"
        : "+f"(c[0]), "+f"(c[1]), "+f"(c[2]), "+f"(c[3])
        : "r"(a[0]), "r"(a[1]), "r"(a[2]), "r"(a[3]), "r"(b[0]), "r"(b[1]));
}

// =====================================================================
// conv1x1 as tf32 tensor-core GEMM
// =====================================================================
#define A_STR 36
#define B_STR 132

template<int EPI>
__global__ void __launch_bounds__(256) conv1x1_mma(
    const float* __restrict__ in, const float* __restrict__ w,
    const float* __restrict__ bias, float* __restrict__ out,
    const float* __restrict__ mask,
    int Cin, int P,
    size_t inBS, size_t outBS, size_t wBS, size_t maskBS)
{
    const int b = blockIdx.z;
    in  += (size_t)b * inBS;
    out += (size_t)b * outBS;
    w   += (size_t)b * wBS;
    if (EPI == 2) mask += (size_t)b * maskBS;

    const int p0 = blockIdx.x * 128;
    const int o0 = blockIdx.y * 128;

    __shared__ uint32_t As[128 * A_STR];
    __shared__ uint32_t Bs[32 * B_STR];

    const int t = threadIdx.x;
    const int lane = t & 31;
    const int wrp  = t >> 5;
    const int wm   = wrp & 3;
    const int wn   = wrp >> 2;
    const int gid  = lane >> 2;
    const int tig  = lane & 3;

    float acc[2][8][4];
#pragma unroll
    for (int i = 0; i < 2; i++)
#pragma unroll
        for (int j = 0; j < 8; j++)
#pragma unroll
            for (int r = 0; r < 4; r++) acc[i][j][r] = 0.f;

    const int nStages = Cin >> 5;
    for (int stage = 0; stage < nStages; stage++) {
        const int cbase = stage << 5;
        {
            const float* wb = w + (size_t)o0 * Cin + cbase;
#pragma unroll
            for (int i = 0; i < 4; i++) {
                const int slot = t + i * 256;
                const int o  = slot >> 3;
                const int c4 = slot & 7;
                const float4 v = *(const float4*)(wb + (size_t)o * Cin + c4 * 4);
                uint32_t* dst = As + o * A_STR + c4 * 4;
                dst[0] = f2tf32(v.x); dst[1] = f2tf32(v.y);
                dst[2] = f2tf32(v.z); dst[3] = f2tf32(v.w);
            }
        }
        {
            const float* ib = in + (size_t)cbase * P + p0;
#pragma unroll
            for (int i = 0; i < 4; i++) {
                const int slot = t + i * 256;
                const int c  = slot >> 5;
                const int p4 = slot & 31;
                const float4 v = *(const float4*)(ib + (size_t)c * P + p4 * 4);
                uint32_t* dst = Bs + c * B_STR + p4 * 4;
                dst[0] = f2tf32(v.x); dst[1] = f2tf32(v.y);
                dst[2] = f2tf32(v.z); dst[3] = f2tf32(v.w);
            }
        }
        __syncthreads();

#pragma unroll
        for (int k0 = 0; k0 < 32; k0 += 8) {
            uint32_t af[2][4];
#pragma unroll
            for (int tm = 0; tm < 2; tm++) {
                const int rb = wm * 32 + tm * 16;
                af[tm][0] = As[(rb + gid    ) * A_STR + k0 + tig    ];
                af[tm][1] = As[(rb + gid + 8) * A_STR + k0 + tig    ];
                af[tm][2] = As[(rb + gid    ) * A_STR + k0 + tig + 4];
                af[tm][3] = As[(rb + gid + 8) * A_STR + k0 + tig + 4];
            }
#pragma unroll
            for (int tn = 0; tn < 8; tn++) {
                uint32_t bf[2];
                const int col = wn * 64 + tn * 8 + gid;
                bf[0] = Bs[(k0 + tig    ) * B_STR + col];
                bf[1] = Bs[(k0 + tig + 4) * B_STR + col];
#pragma unroll
                for (int tm = 0; tm < 2; tm++)
                    mma_tf32(acc[tm][tn], af[tm], bf);
            }
        }
        __syncthreads();
    }

#pragma unroll
    for (int tm = 0; tm < 2; tm++) {
        const int oA = o0 + wm * 32 + tm * 16 + gid;
        const int oB = oA + 8;
        const float bvA = __ldg(bias + oA);
        const float bvB = __ldg(bias + oB);
#pragma unroll
        for (int tn = 0; tn < 8; tn++) {
            const int p = p0 + wn * 64 + tn * 8 + tig * 2;
            float v0 = acc[tm][tn][0] + bvA;
            float v1 = acc[tm][tn][1] + bvA;
            float v2 = acc[tm][tn][2] + bvB;
            float v3 = acc[tm][tn][3] + bvB;
            if (EPI == 1) {
                v0 = sigm(v0); v1 = sigm(v1); v2 = sigm(v2); v3 = sigm(v3);
            }
            if (EPI == 2) {
                const float2 iA = *(const float2*)(in + (size_t)oA * P + p);
                const float2 iB = *(const float2*)(in + (size_t)oB * P + p);
                const float2 mA = *(const float2*)(mask + (size_t)oA * P + p);
                const float2 mB = *(const float2*)(mask + (size_t)oB * P + p);
                v0 = iA.x + v0 * mA.x; v1 = iA.y + v1 * mA.y;
                v2 = iB.x + v2 * mB.x; v3 = iB.y + v3 * mB.y;
            }
            *(float2*)(out + (size_t)oA * P + p) = make_float2(v0, v1);
            *(float2*)(out + (size_t)oB * P + p) = make_float2(v2, v3);
        }
    }
}

// =====================================================================
// depthwise 3x3 on k,v channels only (q is fused into dwconv_dwt_k)
// =====================================================================
__global__ void __launch_bounds__(256) dwconv3_k(
    const float* __restrict__ in, const float* __restrict__ wk,
    const float* __restrict__ wv, float* __restrict__ out)
{
    const int zc2 = blockIdx.z;              // b*2C + ch2
    const int b   = zc2 / (2*Cc);
    const int ch2 = zc2 % (2*Cc);
    const int cm  = ch2 % Cc;
    const float* ws = (ch2 < Cc) ? wk : wv;
    float wgt[9];
#pragma unroll
    for (int i=0;i<9;i++) wgt[i] = __ldg(ws + cm*9 + i);

    const size_t off = ((size_t)b*3*Cc + Cc + ch2)*Nf;
    const float* ip = in  + off;
    float*       op = out + off;

    const int x0 = (blockIdx.x*32 + threadIdx.x)*4;
    const int y  = blockIdx.y*8  + threadIdx.y;

    float r[3][6];
#pragma unroll
    for (int dy=0; dy<3; dy++) {
        const int yy = y + dy - 1;
        const bool rv = (unsigned)yy < (unsigned)Hf;
        const float* rp = ip + (size_t)yy*Wf;
#pragma unroll
        for (int j=0; j<6; j++) {
            const int xx = x0 + j - 1;
            r[dy][j] = (rv && (unsigned)xx < (unsigned)Wf) ? __ldg(rp + xx) : 0.f;
        }
    }
    float o[4] = {0.f,0.f,0.f,0.f};
#pragma unroll
    for (int dy=0; dy<3; dy++)
#pragma unroll
        for (int dx=0; dx<3; dx++) {
            const float wv_ = wgt[dy*3+dx];
#pragma unroll
            for (int j=0; j<4; j++) o[j] = fmaf(r[dy][j+dx], wv_, o[j]);
        }
    *(float4*)(op + (size_t)y*Wf + x0) = make_float4(o[0],o[1],o[2],o[3]);
}

// =====================================================================
// fused: depthwise 3x3 on q + Haar DWT (q full-res never materialized)
// =====================================================================
__global__ void __launch_bounds__(256) dwconv_dwt_k(
    const float* __restrict__ in, const float* __restrict__ wq,
    float* __restrict__ ll, float* __restrict__ lh,
    float* __restrict__ hl, float* __restrict__ hh)
{
    const int zc = blockIdx.z;               // b*C + ch
    const int b = zc / Cc, ch = zc % Cc;
    float wgt[9];
#pragma unroll
    for (int i=0;i<9;i++) wgt[i] = __ldg(wq + ch*9 + i);

    const float* ip = in + ((size_t)b*3*Cc + ch)*Nf;
    const size_t ho = (size_t)zc*Nh2;

    const int xh = blockIdx.x*32 + threadIdx.x;   // half-res coords
    const int yh = blockIdx.y*8  + threadIdx.y;
    const int x0 = xh*2, y0 = yh*2;

    float r[4][4];
#pragma unroll
    for (int dy=0; dy<4; dy++) {
        const int yy = y0 + dy - 1;
        const bool rv = (unsigned)yy < (unsigned)Hf;
        const float* rp = ip + (size_t)yy*Wf;
#pragma unroll
        for (int dx=0; dx<4; dx++) {
            const int xx = x0 + dx - 1;
            r[dy][dx] = (rv && (unsigned)xx < (unsigned)Wf) ? __ldg(rp + xx) : 0.f;
        }
    }
    float o[2][2];
#pragma unroll
    for (int qy=0; qy<2; qy++)
#pragma unroll
        for (int qx=0; qx<2; qx++) {
            float s = 0.f;
#pragma unroll
            for (int ky=0; ky<3; ky++)
#pragma unroll
                for (int kx=0; kx<3; kx++)
                    s = fmaf(r[qy+ky][qx+kx], wgt[ky*3+kx], s);
            o[qy][qx] = s;
        }
    const float a = o[0][0], bb = o[0][1], c = o[1][0], d = o[1][1];
    const size_t p = ho + (size_t)yh*Wh + xh;
    ll[p] = (a+bb+c+d)*0.5f;
    lh[p] = (a+bb-c-d)*0.5f;
    hl[p] = (a-bb+c-d)*0.5f;
    hh[p] = (a-bb-c+d)*0.5f;
}

// =====================================================================
// smem-tiled single-stage gated conv.
// =====================================================================
template<int KH,int KW>
__global__ void __launch_bounds__(256) gated_s(
    const float* __restrict__ in, const float* __restrict__ w,
    float* __restrict__ out)
{
    constexpr int HALO_Y = KH/2, HALO_X = KW/2;
    constexpr int TR = 8 + KH - 1;
    constexpr int TC = 128 + KW - 1;
    __shared__ float sm[TR][TC];
    __shared__ float wsm[2][KH*KW];

    const int zc = blockIdx.z;
    const int ch = zc % Cc;
    const int t  = threadIdx.y*32 + threadIdx.x;
    if (t < 2*KH*KW) {
        const int br = t / (KH*KW), i = t % (KH*KW);
        wsm[br][i] = __ldg(w + (size_t)br*Cc*KH*KW + (size_t)ch*KH*KW + i);
    }

    const float* ip = in + (size_t)zc*Nh2;
    const int Y0 = blockIdx.y*8;

    for (int idx = t; idx < TR*TC; idx += 256) {
        const int r = idx / TC, c = idx % TC;
        const int gy = Y0 - HALO_Y + r, gx = c - HALO_X;
        sm[r][c] = ((unsigned)gy < (unsigned)Hh && (unsigned)gx < (unsigned)Wh)
                   ? __ldg(ip + (size_t)gy*Wh + gx) : 0.f;
    }
    __syncthreads();

    const int ty = threadIdx.y;
    const int x0 = threadIdx.x*4;
    float s0[4] = {0,0,0,0}, s1[4] = {0,0,0,0};
#pragma unroll
    for (int ky=0; ky<KH; ky++) {
        float row[KW+3];
#pragma unroll
        for (int j=0; j<KW+3; j++) row[j] = sm[ty+ky][x0+j];
#pragma unroll
        for (int kx=0; kx<KW; kx++) {
            const float a0 = wsm[0][ky*KW+kx], a1 = wsm[1][ky*KW+kx];
#pragma unroll
            for (int j=0; j<4; j++) {
                s0[j] = fmaf(row[j+kx], a0, s0[j]);
                s1[j] = fmaf(row[j+kx], a1, s1[j]);
            }
        }
    }
    float4 o;
    o.x = s0[0]*sigm(s1[0]); o.y = s0[1]*sigm(s1[1]);
    o.z = s0[2]*sigm(s1[2]); o.w = s0[3]*sigm(s1[3]);
    *(float4*)(out + (size_t)zc*Nh2 + (size_t)(Y0+ty)*Wh + x0) = o;
}

// =====================================================================
// fused dual 2-stage gated chains (llr & llh both read ll)
// =====================================================================
__global__ void __launch_bounds__(256) gated2_dual_k(
    const float* __restrict__ in,
    const float* __restrict__ wA, const float* __restrict__ wB,
    float* __restrict__ outA, float* __restrict__ outB)
{
    __shared__ float sm[12][132];
    __shared__ float midA[10][132];
    __shared__ float midB[10][132];
    __shared__ float wsm[8][9];

    const int zc = blockIdx.z;
    const int ch = zc % Cc;
    const int t  = threadIdx.y*32 + threadIdx.x;

    if (t < 72) {
        const int set = t / 9, i = t % 9;
        const float* base = (set < 4) ? wA : wB;
        const int s4 = set & 3;
        wsm[set][i] = __ldg(base + (size_t)s4*Cc*9 + (size_t)ch*9 + i);
    }

    const float* ip = in + (size_t)zc*Nh2;
    const int Y0 = blockIdx.y*8;

    for (int idx = t; idx < 12*132; idx += 256) {
        const int r = idx / 132, c = idx % 132;
        const int gy = Y0 - 2 + r, gx = c - 2;
        sm[r][c] = ((unsigned)gy < (unsigned)Hh && (unsigned)gx < (unsigned)Wh)
                   ? __ldg(ip + (size_t)gy*Wh + gx) : 0.f;
    }
    __syncthreads();

    for (int idx = t; idx < 10*130; idx += 256) {
        const int r = idx / 130, c = idx % 130;
        const int gy = Y0 - 1 + r, gx = c - 1;
        float a0=0, a1=0, b0=0, b1=0;
        if ((unsigned)gy < (unsigned)Hh && (unsigned)gx < (unsigned)Wh) {
#pragma unroll
            for (int ky=0; ky<3; ky++)
#pragma unroll
                for (int kx=0; kx<3; kx++) {
                    const float v = sm[r+ky][c+kx];
                    const int i = ky*3+kx;
                    a0 = fmaf(v, wsm[0][i], a0);
                    a1 = fmaf(v, wsm[1][i], a1);
                    b0 = fmaf(v, wsm[4][i], b0);
                    b1 = fmaf(v, wsm[5][i], b1);
                }
        }
        midA[r][c] = a0 * sigm(a1);
        midB[r][c] = b0 * sigm(b1);
    }
    __syncthreads();

    const int ty = threadIdx.y;
    const int x0 = threadIdx.x*4;
    float sA0[4]={0,0,0,0}, sA1[4]={0,0,0,0}, sB0[4]={0,0,0,0}, sB1[4]={0,0,0,0};
#pragma unroll
    for (int ky=0; ky<3; ky++) {
        float rA[6], rB[6];
#pragma unroll
        for (int j=0; j<6; j++) { rA[j] = midA[ty+ky][x0+j]; rB[j] = midB[ty+ky][x0+j]; }
#pragma unroll
        for (int kx=0; kx<3; kx++) {
            const int i = ky*3+kx;
            const float a2_0 = wsm[2][i], a2_1 = wsm[3][i];
            const float b2_0 = wsm[6][i], b2_1 = wsm[7][i];
#pragma unroll
            for (int j=0; j<4; j++) {
                sA0[j] = fmaf(rA[j+kx], a2_0, sA0[j]);
                sA1[j] = fmaf(rA[j+kx], a2_1, sA1[j]);
                sB0[j] = fmaf(rB[j+kx], b2_0, sB0[j]);
                sB1[j] = fmaf(rB[j+kx], b2_1, sB1[j]);
            }
        }
    }
    const size_t op = (size_t)zc*Nh2 + (size_t)(Y0+ty)*Wh + x0;
    float4 oA, oB;
    oA.x = sA0[0]*sigm(sA1[0]); oA.y = sA0[1]*sigm(sA1[1]);
    oA.z = sA0[2]*sigm(sA1[2]); oA.w = sA0[3]*sigm(sA1[3]);
    oB.x = sB0[0]*sigm(sB1[0]); oB.y = sB0[1]*sigm(sB1[1]);
    oB.z = sB0[2]*sigm(sB1[2]); oB.w = sB0[3]*sigm(sB1[3]);
    *(float4*)(outA + op) = oA;
    *(float4*)(outB + op) = oB;
}

// =====================================================================
// inverse DWT with masks, 2 px/thread
// =====================================================================
__global__ void __launch_bounds__(256) idwt_k(
    const float* __restrict__ ll, const float* __restrict__ lh,
    const float* __restrict__ hl, const float* __restrict__ hh,
    const float* __restrict__ masks, float* __restrict__ out)
{
    const int zc = blockIdx.z;
    const int b = zc / Cc, ch = zc % Cc;
    const size_t hp = (size_t)zc*Nh2;
    const float* mb = masks + (size_t)b*5*Cc*Nh2;

    const int x0 = (blockIdx.x*32 + threadIdx.x)*2;
    const int y  = blockIdx.y*8  + threadIdx.y;
    const size_t p = (size_t)y*Wh + x0;

    const float2 vll = *(const float2*)(ll+hp+p);
    float2 vlh = *(const float2*)(lh+hp+p);
    float2 vhl = *(const float2*)(hl+hp+p);
    float2 vhh = *(const float2*)(hh+hp+p);
    const float2 m1 = *(const float2*)(mb + (size_t)(  Cc+ch)*Nh2 + p);
    const float2 m2 = *(const float2*)(mb + (size_t)(2*Cc+ch)*Nh2 + p);
    const float2 m3 = *(const float2*)(mb + (size_t)(3*Cc+ch)*Nh2 + p);
    vlh.x *= m1.x; vlh.y *= m1.y;
    vhl.x *= m2.x; vhl.y *= m2.y;
    vhh.x *= m3.x; vhh.y *= m3.y;

    float* op = out + (size_t)zc*Nf;
    float4 t0, t1;
    t0.x = (vll.x+vlh.x+vhl.x+vhh.x)*0.5f;
    t0.y = (vll.x+vlh.x-vhl.x-vhh.x)*0.5f;
    t0.z = (vll.y+vlh.y+vhl.y+vhh.y)*0.5f;
    t0.w = (vll.y+vlh.y-vhl.y-vhh.y)*0.5f;
    t1.x = (vll.x-vlh.x+vhl.x-vhh.x)*0.5f;
    t1.y = (vll.x-vlh.x-vhl.x+vhh.x)*0.5f;
    t1.z = (vll.y-vlh.y+vhl.y-vhh.y)*0.5f;
    t1.w = (vll.y-vlh.y-vhl.y+vhh.y)*0.5f;
    *(float4*)(op + (size_t)(2*y)*Wf   + 2*x0) = t0;
    *(float4*)(op + (size_t)(2*y+1)*Wf + 2*x0) = t1;
}

// =====================================================================
// gram pass (float4 staging)
// =====================================================================
#define GRAM_TILES 8
__global__ void __launch_bounds__(256) gram_k(const float* __restrict__ q,
                                              const float* __restrict__ kall,
                                              float* __restrict__ gram)
{
    const int h = blockIdx.y, b = blockIdx.z;
    const float* qb = q    + (size_t)b*Cc*Nf            + (size_t)h*HD*Nf;
    const float* kb = kall + (size_t)b*3*Cc*Nf + (size_t)Cc*Nf + (size_t)h*HD*Nf;

    __shared__ float qs[16][132];
    __shared__ float ks[16][132];

    const int t = threadIdx.x;
    const int i = t >> 4, j = t & 15;
    float accS = 0.f, accQ = 0.f, accK = 0.f;

    const int n0base = blockIdx.x * (GRAM_TILES*128);
    for (int tile=0; tile<GRAM_TILES; tile++) {
        const int n0 = n0base + tile*128;
#pragma unroll
        for (int e=0; e<2; e++) {
            const int idx = t + e*256;
            const int r = idx >> 5, c4 = idx & 31;
            const float4 vq = *(const float4*)(qb + (size_t)r*Nf + n0 + c4*4);
            const float4 vk = *(const float4*)(kb + (size_t)r*Nf + n0 + c4*4);
            *(float4*)&qs[r][c4*4] = vq;
            *(float4*)&ks[r][c4*4] = vk;
        }
        __syncthreads();
#pragma unroll 8
        for (int nn=0; nn<128; nn++) {
            const float qv = qs[i][nn];
            const float kv = ks[j][nn];
            accS = fmaf(qv, kv, accS);
            if (j == 0) accQ = fmaf(qv, qv, accQ);
            if (i == 0) accK = fmaf(kv, kv, accK);
        }
        __syncthreads();
    }
    float* gp = gram + (size_t)(b*NHh + h)*288;
    atomicAdd(gp + i*16 + j, accS);
    if (j == 0) atomicAdd(gp + 256 + i, accQ);
    if (i == 0) atomicAdd(gp + 272 + j, accK);
}

// =====================================================================
// softmax + fold w_out
// =====================================================================
__global__ void attw_k(const float* __restrict__ gram,
                       const float* __restrict__ temp,
                       const float* __restrict__ wout,
                       float* __restrict__ weff)
{
    const int b = blockIdx.x;
    __shared__ float att[NHh][16][16];
    const int t = threadIdx.x;
    const float* gb = gram + (size_t)b*NHh*288;

    if (t < 128) {
        const int h = t >> 4, i = t & 15;
        const float* gp = gb + h*288;
        const float nq = fmaxf(sqrtf(gp[256+i]), 1e-12f);
        const float tv = temp[h];
        float logit[16];
        float mx = -1e30f;
#pragma unroll
        for (int j=0;j<16;j++) {
            const float nk = fmaxf(sqrtf(gp[272+j]), 1e-12f);
            const float l = gp[i*16+j] / (nq*nk) * tv;
            logit[j] = l;
            mx = fmaxf(mx, l);
        }
        float se = 0.f;
#pragma unroll
        for (int j=0;j<16;j++) { const float e = __expf(logit[j]-mx); logit[j]=e; se+=e; }
        const float inv = 1.f/se;
#pragma unroll
        for (int j=0;j<16;j++) att[h][i][j] = logit[j]*inv;
    }
    __syncthreads();

    float* wb = weff + (size_t)b*Cc*Cc;
    for (int idx = t; idx < Cc*Cc; idx += 256) {
        const int o = idx >> 7, cp = idx & 127;
        const int h = cp >> 4, j = cp & 15;
        float s = 0.f;
#pragma unroll
        for (int i=0;i<16;i++)
            s = fmaf(wout[(size_t)o*Cc + h*16 + i], att[h][i][j], s);
        wb[idx] = s;
    }
}

// =====================================================================
// host launch
// =====================================================================
extern "C" void kernel_launch(void* const* d_in, const int* in_sizes, int n_in,
                              void* d_out, int out_size)
{
    const float* x      = (const float*)d_in[0];
    const float* prior  = (const float*)d_in[1];
    const float* w_lin  = (const float*)d_in[2];
    const float* b_lin  = (const float*)d_in[3];
    const float* w_qd   = (const float*)d_in[4];
    const float* w_kd   = (const float*)d_in[5];
    const float* w_vd   = (const float*)d_in[6];
    const float* gw_llr = (const float*)d_in[7];
    const float* gw_llh = (const float*)d_in[8];
    const float* gw_lh  = (const float*)d_in[9];
    const float* gw_hl  = (const float*)d_in[10];
    const float* gw_hh  = (const float*)d_in[11];
    const float* w_prior= (const float*)d_in[12];
    const float* b_prior= (const float*)d_in[13];
    const float* w_pw1  = (const float*)d_in[14];
    const float* b_pw1  = (const float*)d_in[15];
    const float* w_pw2  = (const float*)d_in[16];
    const float* b_pw2  = (const float*)d_in[17];
    const float* w_cat  = (const float*)d_in[18];
    const float* b_cat  = (const float*)d_in[19];
    const float* temper = (const float*)d_in[20];
    const float* w_out  = (const float*)d_in[21];
    const float* b_out  = (const float*)d_in[22];

    float *qkv, *qkvd, *hbuf, *masks, *qcat, *qfull, *gram, *weff;
    cudaGetSymbolAddress((void**)&qkv,   g_qkv);
    cudaGetSymbolAddress((void**)&qkvd,  g_qkvd);
    cudaGetSymbolAddress((void**)&hbuf,  g_hbuf);
    cudaGetSymbolAddress((void**)&masks, g_masks);
    cudaGetSymbolAddress((void**)&qcat,  g_qcat);
    cudaGetSymbolAddress((void**)&qfull, g_qfull);
    cudaGetSymbolAddress((void**)&gram,  g_gram);
    cudaGetSymbolAddress((void**)&weff,  g_weff);

    float* ll   = hbuf + 0*HB;
    float* lh   = hbuf + 1*HB;
    float* hl   = hbuf + 2*HB;
    float* hh   = hbuf + 3*HB;
    float* llrg = hbuf + 5*HB;
    float* llhg = hbuf + 6*HB;
    float* lhg  = hbuf + 7*HB;
    float* hlg  = hbuf + 8*HB;
    float* hhg  = hbuf + 9*HB;

    const size_t fullBS = (size_t)Cc*Nf;
    const size_t qkvBS  = (size_t)3*Cc*Nf;
    const size_t halfBS = (size_t)Cc*Nh2;
    const size_t mBS    = (size_t)5*Cc*Nh2;
    const size_t catBS  = (size_t)2*Cc*Nh2;

    // 1. qkv = conv1x1(x, w_lin) + b_lin
    conv1x1_mma<0><<<dim3(Nf/128, 3, Bq), 256>>>(
        x, w_lin, b_lin, qkv, nullptr, Cc, Nf, fullBS, qkvBS, 0, 0);

    // 2a. depthwise 3x3 on k,v
    dwconv3_k<<<dim3(Wf/128, Hf/8, Bq*2*Cc), dim3(32,8)>>>(qkv, w_kd, w_vd, qkvd);
    // 2b. fused depthwise 3x3 on q + Haar DWT
    dwconv_dwt_k<<<dim3(Wh/32, Hh/8, Bq*Cc), dim3(32,8)>>>(qkv, w_qd, ll, lh, hl, hh);

    // 3. gated chains
    dim3 gg(1, Hh/8, Bq*Cc), bg(32,8);
    gated2_dual_k<<<gg, bg>>>(ll, gw_llr, gw_llh, llrg, llhg);
    gated_s<3,5><<<gg, bg>>>(lh, gw_lh, lhg);
    gated_s<5,3><<<gg, bg>>>(hl, gw_hl, hlg);
    gated_s<3,3><<<gg, bg>>>(hh, gw_hh, hhg);

    // 4. masks = sigmoid(conv1x1(prior, w_prior))
    conv1x1_mma<1><<<dim3(Nh2/128, 5, Bq), 256>>>(
        prior, w_prior, b_prior, masks, nullptr, Cc, Nh2, halfBS, mBS, 0, 0);

    // 5. pw residual-mask blocks -> qcat
    conv1x1_mma<2><<<dim3(Nh2/128, 1, Bq), 256>>>(
        llrg, w_pw1, b_pw1, qcat, masks, Cc, Nh2, halfBS, catBS, 0, mBS);
    conv1x1_mma<2><<<dim3(Nh2/128, 1, Bq), 256>>>(
        llhg, w_pw2, b_pw2, qcat + (size_t)Cc*Nh2, masks + (size_t)4*Cc*Nh2, Cc, Nh2,
        halfBS, catBS, 0, mBS);

    // 6. q_ll = conv1x1(cat, w_cat) + b_cat
    conv1x1_mma<0><<<dim3(Nh2/128, 1, Bq), 256>>>(
        qcat, w_cat, b_cat, ll, nullptr, 2*Cc, Nh2, catBS, halfBS, 0, 0);

    // 7. inverse DWT with masks
    idwt_k<<<dim3(Wh/64, Hh/8, Bq*Cc), dim3(32,8)>>>(ll, lhg, hlg, hhg, masks, qfull);

    // 8. gram matrices + norms
    cudaMemsetAsync(gram, 0, (size_t)Bq*NHh*288*sizeof(float));
    gram_k<<<dim3(Nf/(GRAM_TILES*128), NHh, Bq), 256>>>(qfull, qkvd, gram);

    // 9. softmax + fold into Weff
    attw_k<<<Bq, 256>>>(gram, temper, w_out, weff);

    // 10. final: out = Weff_b @ v + b_out
    conv1x1_mma<0><<<dim3(Nf/128, 1, Bq), 256>>>(
        qkvd + (size_t)2*Cc*Nf, weff, b_out, (float*)d_out, nullptr, Cc, Nf,
        qkvBS, fullBS, (size_t)Cc*Cc, 0);

    // 11. second output = prior pass-through
    const size_t xel = (size_t)in_sizes[0];
    const size_t pel = (size_t)in_sizes[1];
    if ((size_t)out_size >= xel + pel) {
        cudaMemcpyAsync((float*)d_out + xel, prior, pel*sizeof(float),
                        cudaMemcpyDeviceToDevice);
    }
}